// round 4
// baseline (speedup 1.0000x reference)
#include <cuda_runtime.h>
#include <cuda_bf16.h>
#include <cstdint>

// ---------------------------------------------------------------------------
// B=4, C=512, C8=64, N=4096
// 1) f = Wf@x+bf (fp32 SIMT), g = Wg@x+bg (fp32 SIMT)
//    xb = bf16(x), Whb = bf16(Wh); hv = Whb@xb+bh  (HMMA, bf16 out)
// 2) logits = f^T g (fp32 SIMT)
// 3) softmax rows (fp32 in, bf16 out)
// 4) out = gamma * (hv @ attn) + x   (HMMA bf16, fp32 accum, fused epilogue)
// NOTE: tcgen05 is NOT available through this toolchain (PTX target is
// compute_103 without the 'a' feature set) -> use mma.sync (HMMA) instead.
// ---------------------------------------------------------------------------

#define BATCH 4
#define NC    512
#define NC8   64
#define NTOK  4096

__device__ float          d_f     [(long)BATCH * NC8 * NTOK];   //   4 MB
__device__ float          d_g     [(long)BATCH * NC8 * NTOK];   //   4 MB
__device__ __nv_bfloat16  d_xb    [(long)BATCH * NC  * NTOK];   //  16 MB
__device__ __nv_bfloat16  d_Whb   [(long)NC * NC];              // 512 KB
__device__ __nv_bfloat16  d_hvb   [(long)BATCH * NC  * NTOK];   //  16 MB
__device__ float          d_logits[(long)BATCH * NTOK * NTOK];  // 256 MB
__device__ __nv_bfloat16  d_attnb [(long)BATCH * NTOK * NTOK];  // 128 MB

// ===========================================================================
// fp32 -> bf16 convert (vectorized)
// ===========================================================================
__global__ __launch_bounds__(256) void f32_to_bf16(
    const float* __restrict__ in, __nv_bfloat16* __restrict__ out, long n4)
{
    long i = (long)blockIdx.x * 256 + threadIdx.x;
    if (i >= n4) return;
    float4 v = ((const float4*)in)[i];
    __nv_bfloat162 p[2];
    p[0] = __floats2bfloat162_rn(v.x, v.y);
    p[1] = __floats2bfloat162_rn(v.z, v.w);
    ((uint2*)out)[i] = *(uint2*)p;
}

// ===========================================================================
// SIMT fp32 GEMM (f/g projections + logits)
// ===========================================================================
#define BM 128
#define BN 128
#define BK 16
#define TM 8
#define TN 8

template<bool AK, int EPI>
__global__ __launch_bounds__(256) void gemm128(
    const float* __restrict__ A, long sA, int ldA,
    const float* __restrict__ B, long sB, int ldB,
    float*       __restrict__ C, long sC, int ldC,
    const float* __restrict__ bias,
    int M, int K)
{
    __shared__ float As[BK][BM];
    __shared__ float Bs[BK][BN];

    const int b  = blockIdx.z;
    const int m0 = blockIdx.y * BM;
    const int n0 = blockIdx.x * BN;

    A += (long)b * sA;
    B += (long)b * sB;
    C += (long)b * sC;

    const int tid = threadIdx.x;
    const int tx  = tid & 15;
    const int ty  = tid >> 4;

    float acc[TM][TN];
    #pragma unroll
    for (int i = 0; i < TM; i++)
        #pragma unroll
        for (int j = 0; j < TN; j++) acc[i][j] = 0.f;

    for (int k0 = 0; k0 < K; k0 += BK) {
        if (AK) {
            #pragma unroll
            for (int i = 0; i < 2; i++) {
                int idx = tid * 2 + i;
                int r   = idx >> 5;
                int c4  = idx & 31;
                float4 v = *(const float4*)&A[(long)(k0 + r) * ldA + m0 + c4 * 4];
                *(float4*)&As[r][c4 * 4] = v;
            }
        } else {
            #pragma unroll
            for (int i = 0; i < 2; i++) {
                int idx = tid * 2 + i;
                int r   = idx >> 2;
                int c4  = idx & 3;
                float4 v = make_float4(0.f, 0.f, 0.f, 0.f);
                if (m0 + r < M)
                    v = *(const float4*)&A[(long)(m0 + r) * ldA + k0 + c4 * 4];
                As[c4 * 4 + 0][r] = v.x;
                As[c4 * 4 + 1][r] = v.y;
                As[c4 * 4 + 2][r] = v.z;
                As[c4 * 4 + 3][r] = v.w;
            }
        }
        #pragma unroll
        for (int i = 0; i < 2; i++) {
            int idx = tid * 2 + i;
            int r   = idx >> 5;
            int c4  = idx & 31;
            float4 v = *(const float4*)&B[(long)(k0 + r) * ldB + n0 + c4 * 4];
            *(float4*)&Bs[r][c4 * 4] = v;
        }
        __syncthreads();

        #pragma unroll
        for (int kk = 0; kk < BK; kk++) {
            float a[TM], bb[TN];
            #pragma unroll
            for (int i = 0; i < TM; i++) a[i] = As[kk][ty * TM + i];
            #pragma unroll
            for (int j = 0; j < TN; j++) bb[j] = Bs[kk][tx * TN + j];
            #pragma unroll
            for (int i = 0; i < TM; i++)
                #pragma unroll
                for (int j = 0; j < TN; j++)
                    acc[i][j] += a[i] * bb[j];
        }
        __syncthreads();
    }

    #pragma unroll
    for (int i = 0; i < TM; i++) {
        int m = m0 + ty * TM + i;
        if (m >= M) continue;
        float bv = (EPI == 0) ? bias[m] : 0.f;
        #pragma unroll
        for (int j = 0; j < TN; j += 4) {
            int n = n0 + tx * TN + j;
            float4 v;
            v.x = acc[i][j + 0] + bv;
            v.y = acc[i][j + 1] + bv;
            v.z = acc[i][j + 2] + bv;
            v.w = acc[i][j + 3] + bv;
            *(float4*)&C[(long)m * ldC + n] = v;
        }
    }
}

// ===========================================================================
// Row softmax: fp32 logits in, bf16 attn out.
// ===========================================================================
__global__ __launch_bounds__(256) void softmax_rows(
    const float* __restrict__ logits, __nv_bfloat16* __restrict__ attnb)
{
    const long row = (long)blockIdx.y * NTOK + blockIdx.x;
    const float* p = logits + row * NTOK;
    __nv_bfloat16* q = attnb + row * NTOK;
    const int tid = threadIdx.x;

    float v[16];
    float mx = -3.4e38f;
    #pragma unroll
    for (int t = 0; t < 16; t++) {
        v[t] = p[t * 256 + tid];
        mx = fmaxf(mx, v[t]);
    }

    __shared__ float sred[8];
    #pragma unroll
    for (int o = 16; o > 0; o >>= 1)
        mx = fmaxf(mx, __shfl_xor_sync(0xffffffffu, mx, o));
    if ((tid & 31) == 0) sred[tid >> 5] = mx;
    __syncthreads();
    if (tid == 0) {
        float m2 = sred[0];
        #pragma unroll
        for (int i = 1; i < 8; i++) m2 = fmaxf(m2, sred[i]);
        sred[0] = m2;
    }
    __syncthreads();
    const float rmax = sred[0];
    __syncthreads();

    float s = 0.f;
    #pragma unroll
    for (int t = 0; t < 16; t++) {
        v[t] = __expf(v[t] - rmax);
        s += v[t];
    }
    #pragma unroll
    for (int o = 16; o > 0; o >>= 1)
        s += __shfl_xor_sync(0xffffffffu, s, o);
    if ((tid & 31) == 0) sred[tid >> 5] = s;
    __syncthreads();
    if (tid == 0) {
        float s2 = 0.f;
        #pragma unroll
        for (int i = 0; i < 8; i++) s2 += sred[i];
        sred[0] = s2;
    }
    __syncthreads();
    const float inv = 1.0f / sred[0];

    #pragma unroll
    for (int t = 0; t < 16; t++)
        q[t * 256 + tid] = __float2bfloat16(v[t] * inv);
}

// ===========================================================================
// bf16 HMMA GEMM (mma.sync.m16n8k16), 128x128x32 tiles, 256 threads.
//   C[m,n] = sum_k A[m,k] * B[k,n]
//   A row-major (M x K), B row-major (K x N). ldmatrix.trans handles B.
// EPI=0: C(bf16) = acc + bias[m]
// EPI=2: C(f32)  = gamma[0]*acc + resid[m,n]
// Requires M%128==0, N%128==0, K%32==0.
// ===========================================================================

__device__ __forceinline__ uint32_t smem_u32(const void* p) {
    uint32_t a;
    asm("{ .reg .u64 t; cvta.to.shared.u64 t, %1; cvt.u32.u64 %0, t; }"
        : "=r"(a) : "l"(p));
    return a;
}
__device__ __forceinline__ void cp16(uint32_t s, const void* g) {
    asm volatile("cp.async.cg.shared.global [%0], [%1], 16;" :: "r"(s), "l"(g));
}
__device__ __forceinline__ void ldsm_x4(uint32_t* r, uint32_t a) {
    asm volatile("ldmatrix.sync.aligned.m8n8.x4.shared.b16 {%0,%1,%2,%3}, [%4];"
                 : "=r"(r[0]), "=r"(r[1]), "=r"(r[2]), "=r"(r[3]) : "r"(a));
}
__device__ __forceinline__ void ldsm_x2_t(uint32_t* r, uint32_t a) {
    asm volatile("ldmatrix.sync.aligned.m8n8.x2.trans.shared.b16 {%0,%1}, [%2];"
                 : "=r"(r[0]), "=r"(r[1]) : "r"(a));
}
__device__ __forceinline__ void mma_bf16(float* d, const uint32_t* a, const uint32_t* b) {
    asm volatile(
        "mma.sync.aligned.m16n8k16.row.col.f32.bf16.bf16.f32 "
        "{%0,%1,%2,%3}, {%4,%5,%6,%7}, {%8,%9}, {%0,%1,%2,%3};"
        : "+f"(d[0]), "+f"(d[1]), "+f"(d[2]), "+f"(d[3])
        : "r"(a[0]), "r"(a[1]), "r"(a[2]), "r"(a[3]), "r"(b[0]), "r"(b[1]));
}

#define APAD 8
#define BPAD 8
#define ALD  (32 + APAD)    // bf16 elems per A smem row (80 B, 16B-aligned)
#define BLD  (128 + BPAD)   // bf16 elems per B smem row (272 B, 16B-aligned)

template<int EPI>
__global__ __launch_bounds__(256) void gemm_mma(
    const __nv_bfloat16* __restrict__ A, long sA, int ldA,
    const __nv_bfloat16* __restrict__ B, long sB, int ldB,
    void*                __restrict__ Cv, long sC, int ldC,
    const float* __restrict__ bias,
    const float* __restrict__ resid, long sR,
    const float* __restrict__ gamma,
    int K)
{
    __shared__ __nv_bfloat16 As[2][128][ALD];
    __shared__ __nv_bfloat16 Bs[2][32][BLD];

    const int b  = blockIdx.z;
    const int m0 = blockIdx.y * 128;
    const int n0 = blockIdx.x * 128;

    A += (long)b * sA;
    B += (long)b * sB;

    const int tid  = threadIdx.x;
    const int wid  = tid >> 5;
    const int lane = tid & 31;
    const int wm   = (wid >> 2) * 64;   // warp M offset (0/64)
    const int wn   = (wid & 3) * 32;    // warp N offset (0/32/64/96)

    float acc[4][4][4];
    #pragma unroll
    for (int i = 0; i < 4; i++)
        #pragma unroll
        for (int j = 0; j < 4; j++)
            #pragma unroll
            for (int r = 0; r < 4; r++) acc[i][j][r] = 0.f;

    // cp.async indexing (per thread: 2 A segs + 2 B segs of 16B each)
    const int aseg0 = tid * 2;                 // 0..511
    const int bseg0 = tid * 2;

    auto load_stage = [&](int st, int k0) {
        #pragma unroll
        for (int p = 0; p < 2; p++) {
            int seg = aseg0 + p;
            int r = seg >> 2, sc = seg & 3;
            cp16(smem_u32(&As[st][r][sc * 8]),
                 A + (long)(m0 + r) * ldA + k0 + sc * 8);
        }
        #pragma unroll
        for (int p = 0; p < 2; p++) {
            int seg = bseg0 + p;
            int r = seg >> 4, sc = seg & 15;
            cp16(smem_u32(&Bs[st][r][sc * 8]),
                 B + (long)(k0 + r) * ldB + n0 + sc * 8);
        }
        asm volatile("cp.async.commit_group;");
    };

    const int KT = K >> 5;   // K / 32
    load_stage(0, 0);

    for (int kt = 0; kt < KT; kt++) {
        const int st = kt & 1;
        if (kt + 1 < KT) {
            load_stage(st ^ 1, (kt + 1) * 32);
            asm volatile("cp.async.wait_group 1;");
        } else {
            asm volatile("cp.async.wait_group 0;");
        }
        __syncthreads();

        #pragma unroll
        for (int kk = 0; kk < 2; kk++) {
            uint32_t af[4][4];
            #pragma unroll
            for (int mi = 0; mi < 4; mi++)
                ldsm_x4(af[mi], smem_u32(
                    &As[st][wm + mi * 16 + (lane & 15)][kk * 16 + ((lane >> 4) & 1) * 8]));
            uint32_t bf[4][2];
            #pragma unroll
            for (int ni = 0; ni < 4; ni++)
                ldsm_x2_t(bf[ni], smem_u32(
                    &Bs[st][kk * 16 + (lane & 15)][wn + ni * 8]));
            #pragma unroll
            for (int mi = 0; mi < 4; mi++)
                #pragma unroll
                for (int ni = 0; ni < 4; ni++)
                    mma_bf16(acc[mi][ni], af[mi], bf[ni]);
        }
        __syncthreads();
    }

    // ---- epilogue ----
    const int rbase = lane >> 2;        // 0..7
    const int cbase = (lane & 3) * 2;   // 0,2,4,6
    if (EPI == 0) {
        __nv_bfloat16* Cb = (__nv_bfloat16*)Cv + (long)b * sC;
        #pragma unroll
        for (int mi = 0; mi < 4; mi++) {
            #pragma unroll
            for (int ni = 0; ni < 4; ni++) {
                int row = m0 + wm + mi * 16 + rbase;
                int col = n0 + wn + ni * 8 + cbase;
                float bv0 = bias[row], bv1 = bias[row + 8];
                *(__nv_bfloat162*)&Cb[(long)row * ldC + col] =
                    __floats2bfloat162_rn(acc[mi][ni][0] + bv0, acc[mi][ni][1] + bv0);
                *(__nv_bfloat162*)&Cb[(long)(row + 8) * ldC + col] =
                    __floats2bfloat162_rn(acc[mi][ni][2] + bv1, acc[mi][ni][3] + bv1);
            }
        }
    } else {
        float* Cf = (float*)Cv + (long)b * sC;
        const float* R = resid + (long)b * sR;
        const float gm = gamma[0];
        #pragma unroll
        for (int mi = 0; mi < 4; mi++) {
            #pragma unroll
            for (int ni = 0; ni < 4; ni++) {
                int row = m0 + wm + mi * 16 + rbase;
                int col = n0 + wn + ni * 8 + cbase;
                float2 r0 = *(const float2*)&R[(long)row * ldC + col];
                float2 r1 = *(const float2*)&R[(long)(row + 8) * ldC + col];
                float2 o0, o1;
                o0.x = gm * acc[mi][ni][0] + r0.x;
                o0.y = gm * acc[mi][ni][1] + r0.y;
                o1.x = gm * acc[mi][ni][2] + r1.x;
                o1.y = gm * acc[mi][ni][3] + r1.y;
                *(float2*)&Cf[(long)row * ldC + col] = o0;
                *(float2*)&Cf[(long)(row + 8) * ldC + col] = o1;
            }
        }
    }
}

// ===========================================================================
// kernel_launch  — inputs: x, Wf, bf, Wg, bg, Wh, bh, gamma
// ===========================================================================
extern "C" void kernel_launch(void* const* d_in, const int* in_sizes, int n_in,
                              void* d_out, int out_size)
{
    const float* x     = (const float*)d_in[0];
    const float* Wf    = (const float*)d_in[1];
    const float* bf    = (const float*)d_in[2];
    const float* Wg    = (const float*)d_in[3];
    const float* bg    = (const float*)d_in[4];
    const float* Wh    = (const float*)d_in[5];
    const float* bh    = (const float*)d_in[6];
    const float* gamma = (const float*)d_in[7];
    float* out = (float*)d_out;

    void *pf, *pg, *pxb, *pwh, *ph, *pl, *pab;
    cudaGetSymbolAddress(&pf,  d_f);
    cudaGetSymbolAddress(&pg,  d_g);
    cudaGetSymbolAddress(&pxb, d_xb);
    cudaGetSymbolAddress(&pwh, d_Whb);
    cudaGetSymbolAddress(&ph,  d_hvb);
    cudaGetSymbolAddress(&pl,  d_logits);
    cudaGetSymbolAddress(&pab, d_attnb);
    float* f             = (float*)pf;
    float* g             = (float*)pg;
    __nv_bfloat16* xb    = (__nv_bfloat16*)pxb;
    __nv_bfloat16* Whb   = (__nv_bfloat16*)pwh;
    __nv_bfloat16* hvb   = (__nv_bfloat16*)ph;
    float* logits        = (float*)pl;
    __nv_bfloat16* attnb = (__nv_bfloat16*)pab;

    const long sx  = (long)NC  * NTOK;
    const long sfg = (long)NC8 * NTOK;
    const long sat = (long)NTOK * NTOK;

    // 0) bf16 conversions
    {
        long n4 = (long)BATCH * NC * NTOK / 4;
        f32_to_bf16<<<(unsigned)((n4 + 255) / 256), 256>>>(x, xb, n4);
        long w4 = (long)NC * NC / 4;
        f32_to_bf16<<<(unsigned)((w4 + 255) / 256), 256>>>(Wh, Whb, w4);
    }

    // 1) f/g projections (fp32 SIMT)
    gemm128<false, 0><<<dim3(NTOK / BN, 1, BATCH), 256>>>(
        Wf, 0, NC, x, sx, NTOK, f, sfg, NTOK, bf, NC8, NC);
    gemm128<false, 0><<<dim3(NTOK / BN, 1, BATCH), 256>>>(
        Wg, 0, NC, x, sx, NTOK, g, sfg, NTOK, bg, NC8, NC);

    // 1b) hv = Whb @ xb + bh  (HMMA, bf16 out)
    gemm_mma<0><<<dim3(NTOK / 128, NC / 128, BATCH), 256>>>(
        Whb, 0, NC, xb, sx, NTOK, hvb, sx, NTOK, bh, nullptr, 0, nullptr, NC);

    // 2) logits = f^T g (fp32 SIMT)
    gemm128<true, 1><<<dim3(NTOK / BN, NTOK / BM, BATCH), 256>>>(
        f, sfg, NTOK, g, sfg, NTOK, logits, sat, NTOK, nullptr, NTOK, NC8);

    // 3) softmax (fp32 -> bf16)
    softmax_rows<<<dim3(NTOK, BATCH), 256>>>(logits, attnb);

    // 4) out = gamma * (hvb @ attn) + x  (HMMA, fused epilogue)
    gemm_mma<2><<<dim3(NTOK / 128, NC / 128, BATCH), 256>>>(
        hvb, sx, NTOK, attnb, sat, NTOK, out, sx, NTOK,
        nullptr, x, sx, gamma, NTOK);
}

// round 5
// speedup vs baseline: 1.0035x; 1.0035x over previous
#include <cuda_runtime.h>
#include <cuda_bf16.h>
#include <cstdint>

// ---------------------------------------------------------------------------
// B=4, C=512, C8=64, N=4096
// 1) f = Wf@x+bf (fp32 SIMT), g = Wg@x+bg (fp32 SIMT)
//    xb = bf16(x), Whb = bf16(Wh); hv = Whb@xb+bh  (HMMA, bf16 out)
// 2) logits = f^T g (fp32 SIMT)
// 3) softmax rows (fp32 in, bf16 out)
// 4) out = gamma * (hv @ attn) + x   (HMMA bf16, fp32 accum, fused epilogue)
// NOTE: tcgen05 is NOT available through this toolchain (PTX target is
// compute_103 without the 'a' feature set) -> use mma.sync (HMMA) instead.
// ---------------------------------------------------------------------------

#define BATCH 4
#define NC    512
#define NC8   64
#define NTOK  4096

__device__ float          d_f     [(long)BATCH * NC8 * NTOK];   //   4 MB
__device__ float          d_g     [(long)BATCH * NC8 * NTOK];   //   4 MB
__device__ __nv_bfloat16  d_xb    [(long)BATCH * NC  * NTOK];   //  16 MB
__device__ __nv_bfloat16  d_Whb   [(long)NC * NC];              // 512 KB
__device__ __nv_bfloat16  d_hvb   [(long)BATCH * NC  * NTOK];   //  16 MB
__device__ float          d_logits[(long)BATCH * NTOK * NTOK];  // 256 MB
__device__ __nv_bfloat16  d_attnb [(long)BATCH * NTOK * NTOK];  // 128 MB

// ===========================================================================
// fp32 -> bf16 convert (vectorized)
// ===========================================================================
__global__ __launch_bounds__(256) void f32_to_bf16(
    const float* __restrict__ in, __nv_bfloat16* __restrict__ out, long n4)
{
    long i = (long)blockIdx.x * 256 + threadIdx.x;
    if (i >= n4) return;
    float4 v = ((const float4*)in)[i];
    __nv_bfloat162 p[2];
    p[0] = __floats2bfloat162_rn(v.x, v.y);
    p[1] = __floats2bfloat162_rn(v.z, v.w);
    ((uint2*)out)[i] = *(uint2*)p;
}

// ===========================================================================
// SIMT fp32 GEMM (f/g projections + logits)
// ===========================================================================
#define BM 128
#define BN 128
#define BK 16
#define TM 8
#define TN 8

template<bool AK, int EPI>
__global__ __launch_bounds__(256) void gemm128(
    const float* __restrict__ A, long sA, int ldA,
    const float* __restrict__ B, long sB, int ldB,
    float*       __restrict__ C, long sC, int ldC,
    const float* __restrict__ bias,
    int M, int K)
{
    __shared__ float As[BK][BM];
    __shared__ float Bs[BK][BN];

    const int b  = blockIdx.z;
    const int m0 = blockIdx.y * BM;
    const int n0 = blockIdx.x * BN;

    A += (long)b * sA;
    B += (long)b * sB;
    C += (long)b * sC;

    const int tid = threadIdx.x;
    const int tx  = tid & 15;
    const int ty  = tid >> 4;

    float acc[TM][TN];
    #pragma unroll
    for (int i = 0; i < TM; i++)
        #pragma unroll
        for (int j = 0; j < TN; j++) acc[i][j] = 0.f;

    for (int k0 = 0; k0 < K; k0 += BK) {
        if (AK) {
            #pragma unroll
            for (int i = 0; i < 2; i++) {
                int idx = tid * 2 + i;
                int r   = idx >> 5;
                int c4  = idx & 31;
                float4 v = *(const float4*)&A[(long)(k0 + r) * ldA + m0 + c4 * 4];
                *(float4*)&As[r][c4 * 4] = v;
            }
        } else {
            #pragma unroll
            for (int i = 0; i < 2; i++) {
                int idx = tid * 2 + i;
                int r   = idx >> 2;
                int c4  = idx & 3;
                float4 v = make_float4(0.f, 0.f, 0.f, 0.f);
                if (m0 + r < M)
                    v = *(const float4*)&A[(long)(m0 + r) * ldA + k0 + c4 * 4];
                As[c4 * 4 + 0][r] = v.x;
                As[c4 * 4 + 1][r] = v.y;
                As[c4 * 4 + 2][r] = v.z;
                As[c4 * 4 + 3][r] = v.w;
            }
        }
        #pragma unroll
        for (int i = 0; i < 2; i++) {
            int idx = tid * 2 + i;
            int r   = idx >> 5;
            int c4  = idx & 31;
            float4 v = *(const float4*)&B[(long)(k0 + r) * ldB + n0 + c4 * 4];
            *(float4*)&Bs[r][c4 * 4] = v;
        }
        __syncthreads();

        #pragma unroll
        for (int kk = 0; kk < BK; kk++) {
            float a[TM], bb[TN];
            #pragma unroll
            for (int i = 0; i < TM; i++) a[i] = As[kk][ty * TM + i];
            #pragma unroll
            for (int j = 0; j < TN; j++) bb[j] = Bs[kk][tx * TN + j];
            #pragma unroll
            for (int i = 0; i < TM; i++)
                #pragma unroll
                for (int j = 0; j < TN; j++)
                    acc[i][j] += a[i] * bb[j];
        }
        __syncthreads();
    }

    #pragma unroll
    for (int i = 0; i < TM; i++) {
        int m = m0 + ty * TM + i;
        if (m >= M) continue;
        float bv = (EPI == 0) ? bias[m] : 0.f;
        #pragma unroll
        for (int j = 0; j < TN; j += 4) {
            int n = n0 + tx * TN + j;
            float4 v;
            v.x = acc[i][j + 0] + bv;
            v.y = acc[i][j + 1] + bv;
            v.z = acc[i][j + 2] + bv;
            v.w = acc[i][j + 3] + bv;
            *(float4*)&C[(long)m * ldC + n] = v;
        }
    }
}

// ===========================================================================
// Row softmax: fp32 logits in, bf16 attn out.
// ===========================================================================
__global__ __launch_bounds__(256) void softmax_rows(
    const float* __restrict__ logits, __nv_bfloat16* __restrict__ attnb)
{
    const long row = (long)blockIdx.y * NTOK + blockIdx.x;
    const float* p = logits + row * NTOK;
    __nv_bfloat16* q = attnb + row * NTOK;
    const int tid = threadIdx.x;

    float v[16];
    float mx = -3.4e38f;
    #pragma unroll
    for (int t = 0; t < 16; t++) {
        v[t] = p[t * 256 + tid];
        mx = fmaxf(mx, v[t]);
    }

    __shared__ float sred[8];
    #pragma unroll
    for (int o = 16; o > 0; o >>= 1)
        mx = fmaxf(mx, __shfl_xor_sync(0xffffffffu, mx, o));
    if ((tid & 31) == 0) sred[tid >> 5] = mx;
    __syncthreads();
    if (tid == 0) {
        float m2 = sred[0];
        #pragma unroll
        for (int i = 1; i < 8; i++) m2 = fmaxf(m2, sred[i]);
        sred[0] = m2;
    }
    __syncthreads();
    const float rmax = sred[0];
    __syncthreads();

    float s = 0.f;
    #pragma unroll
    for (int t = 0; t < 16; t++) {
        v[t] = __expf(v[t] - rmax);
        s += v[t];
    }
    #pragma unroll
    for (int o = 16; o > 0; o >>= 1)
        s += __shfl_xor_sync(0xffffffffu, s, o);
    if ((tid & 31) == 0) sred[tid >> 5] = s;
    __syncthreads();
    if (tid == 0) {
        float s2 = 0.f;
        #pragma unroll
        for (int i = 0; i < 8; i++) s2 += sred[i];
        sred[0] = s2;
    }
    __syncthreads();
    const float inv = 1.0f / sred[0];

    #pragma unroll
    for (int t = 0; t < 16; t++)
        q[t * 256 + tid] = __float2bfloat16(v[t] * inv);
}

// ===========================================================================
// bf16 HMMA GEMM (mma.sync.m16n8k16), 128x128x32 tiles, 256 threads.
//   C[m,n] = sum_k A[m,k] * B[k,n]
//   A row-major (M x K), B row-major (K x N). ldmatrix.trans handles B.
// EPI=0: C(bf16) = acc + bias[m]
// EPI=2: C(f32)  = gamma[0]*acc + resid[m,n]
// Requires M%128==0, N%128==0, K%32==0.
// ===========================================================================

__device__ __forceinline__ uint32_t smem_u32(const void* p) {
    uint32_t a;
    asm("{ .reg .u64 t; cvta.to.shared.u64 t, %1; cvt.u32.u64 %0, t; }"
        : "=r"(a) : "l"(p));
    return a;
}
__device__ __forceinline__ void cp16(uint32_t s, const void* g) {
    asm volatile("cp.async.cg.shared.global [%0], [%1], 16;" :: "r"(s), "l"(g));
}
__device__ __forceinline__ void ldsm_x4(uint32_t* r, uint32_t a) {
    asm volatile("ldmatrix.sync.aligned.m8n8.x4.shared.b16 {%0,%1,%2,%3}, [%4];"
                 : "=r"(r[0]), "=r"(r[1]), "=r"(r[2]), "=r"(r[3]) : "r"(a));
}
__device__ __forceinline__ void ldsm_x2_t(uint32_t* r, uint32_t a) {
    asm volatile("ldmatrix.sync.aligned.m8n8.x2.trans.shared.b16 {%0,%1}, [%2];"
                 : "=r"(r[0]), "=r"(r[1]) : "r"(a));
}
__device__ __forceinline__ void mma_bf16(float* d, const uint32_t* a, const uint32_t* b) {
    asm volatile(
        "mma.sync.aligned.m16n8k16.row.col.f32.bf16.bf16.f32 "
        "{%0,%1,%2,%3}, {%4,%5,%6,%7}, {%8,%9}, {%0,%1,%2,%3};"
        : "+f"(d[0]), "+f"(d[1]), "+f"(d[2]), "+f"(d[3])
        : "r"(a[0]), "r"(a[1]), "r"(a[2]), "r"(a[3]), "r"(b[0]), "r"(b[1]));
}

#define APAD 8
#define BPAD 8
#define ALD  (32 + APAD)    // bf16 elems per A smem row (80 B, 16B-aligned)
#define BLD  (128 + BPAD)   // bf16 elems per B smem row (272 B, 16B-aligned)

template<int EPI>
__global__ __launch_bounds__(256) void gemm_mma(
    const __nv_bfloat16* __restrict__ A, long sA, int ldA,
    const __nv_bfloat16* __restrict__ B, long sB, int ldB,
    void*                __restrict__ Cv, long sC, int ldC,
    const float* __restrict__ bias,
    const float* __restrict__ resid, long sR,
    const float* __restrict__ gamma,
    int K)
{
    __shared__ __nv_bfloat16 As[2][128][ALD];
    __shared__ __nv_bfloat16 Bs[2][32][BLD];

    const int b  = blockIdx.z;
    const int m0 = blockIdx.y * 128;
    const int n0 = blockIdx.x * 128;

    A += (long)b * sA;
    B += (long)b * sB;

    const int tid  = threadIdx.x;
    const int wid  = tid >> 5;
    const int lane = tid & 31;
    const int wm   = (wid >> 2) * 64;   // warp M offset (0/64)
    const int wn   = (wid & 3) * 32;    // warp N offset (0/32/64/96)

    float acc[4][4][4];
    #pragma unroll
    for (int i = 0; i < 4; i++)
        #pragma unroll
        for (int j = 0; j < 4; j++)
            #pragma unroll
            for (int r = 0; r < 4; r++) acc[i][j][r] = 0.f;

    // cp.async indexing (per thread: 2 A segs + 2 B segs of 16B each)
    const int aseg0 = tid * 2;                 // 0..511
    const int bseg0 = tid * 2;

    auto load_stage = [&](int st, int k0) {
        #pragma unroll
        for (int p = 0; p < 2; p++) {
            int seg = aseg0 + p;
            int r = seg >> 2, sc = seg & 3;
            cp16(smem_u32(&As[st][r][sc * 8]),
                 A + (long)(m0 + r) * ldA + k0 + sc * 8);
        }
        #pragma unroll
        for (int p = 0; p < 2; p++) {
            int seg = bseg0 + p;
            int r = seg >> 4, sc = seg & 15;
            cp16(smem_u32(&Bs[st][r][sc * 8]),
                 B + (long)(k0 + r) * ldB + n0 + sc * 8);
        }
        asm volatile("cp.async.commit_group;");
    };

    const int KT = K >> 5;   // K / 32
    load_stage(0, 0);

    for (int kt = 0; kt < KT; kt++) {
        const int st = kt & 1;
        if (kt + 1 < KT) {
            load_stage(st ^ 1, (kt + 1) * 32);
            asm volatile("cp.async.wait_group 1;");
        } else {
            asm volatile("cp.async.wait_group 0;");
        }
        __syncthreads();

        #pragma unroll
        for (int kk = 0; kk < 2; kk++) {
            uint32_t af[4][4];
            #pragma unroll
            for (int mi = 0; mi < 4; mi++)
                ldsm_x4(af[mi], smem_u32(
                    &As[st][wm + mi * 16 + (lane & 15)][kk * 16 + ((lane >> 4) & 1) * 8]));
            uint32_t bf[4][2];
            #pragma unroll
            for (int ni = 0; ni < 4; ni++)
                ldsm_x2_t(bf[ni], smem_u32(
                    &Bs[st][kk * 16 + (lane & 15)][wn + ni * 8]));
            #pragma unroll
            for (int mi = 0; mi < 4; mi++)
                #pragma unroll
                for (int ni = 0; ni < 4; ni++)
                    mma_bf16(acc[mi][ni], af[mi], bf[ni]);
        }
        __syncthreads();
    }

    // ---- epilogue ----
    const int rbase = lane >> 2;        // 0..7
    const int cbase = (lane & 3) * 2;   // 0,2,4,6
    if (EPI == 0) {
        __nv_bfloat16* Cb = (__nv_bfloat16*)Cv + (long)b * sC;
        #pragma unroll
        for (int mi = 0; mi < 4; mi++) {
            #pragma unroll
            for (int ni = 0; ni < 4; ni++) {
                int row = m0 + wm + mi * 16 + rbase;
                int col = n0 + wn + ni * 8 + cbase;
                float bv0 = bias[row], bv1 = bias[row + 8];
                *(__nv_bfloat162*)&Cb[(long)row * ldC + col] =
                    __floats2bfloat162_rn(acc[mi][ni][0] + bv0, acc[mi][ni][1] + bv0);
                *(__nv_bfloat162*)&Cb[(long)(row + 8) * ldC + col] =
                    __floats2bfloat162_rn(acc[mi][ni][2] + bv1, acc[mi][ni][3] + bv1);
            }
        }
    } else {
        float* Cf = (float*)Cv + (long)b * sC;
        const float* R = resid + (long)b * sR;
        const float gm = gamma[0];
        #pragma unroll
        for (int mi = 0; mi < 4; mi++) {
            #pragma unroll
            for (int ni = 0; ni < 4; ni++) {
                int row = m0 + wm + mi * 16 + rbase;
                int col = n0 + wn + ni * 8 + cbase;
                float2 r0 = *(const float2*)&R[(long)row * ldC + col];
                float2 r1 = *(const float2*)&R[(long)(row + 8) * ldC + col];
                float2 o0, o1;
                o0.x = gm * acc[mi][ni][0] + r0.x;
                o0.y = gm * acc[mi][ni][1] + r0.y;
                o1.x = gm * acc[mi][ni][2] + r1.x;
                o1.y = gm * acc[mi][ni][3] + r1.y;
                *(float2*)&Cf[(long)row * ldC + col] = o0;
                *(float2*)&Cf[(long)(row + 8) * ldC + col] = o1;
            }
        }
    }
}

// ===========================================================================
// kernel_launch  — inputs: x, Wf, bf, Wg, bg, Wh, bh, gamma
// ===========================================================================
extern "C" void kernel_launch(void* const* d_in, const int* in_sizes, int n_in,
                              void* d_out, int out_size)
{
    const float* x     = (const float*)d_in[0];
    const float* Wf    = (const float*)d_in[1];
    const float* bf    = (const float*)d_in[2];
    const float* Wg    = (const float*)d_in[3];
    const float* bg    = (const float*)d_in[4];
    const float* Wh    = (const float*)d_in[5];
    const float* bh    = (const float*)d_in[6];
    const float* gamma = (const float*)d_in[7];
    float* out = (float*)d_out;

    void *pf, *pg, *pxb, *pwh, *ph, *pl, *pab;
    cudaGetSymbolAddress(&pf,  d_f);
    cudaGetSymbolAddress(&pg,  d_g);
    cudaGetSymbolAddress(&pxb, d_xb);
    cudaGetSymbolAddress(&pwh, d_Whb);
    cudaGetSymbolAddress(&ph,  d_hvb);
    cudaGetSymbolAddress(&pl,  d_logits);
    cudaGetSymbolAddress(&pab, d_attnb);
    float* f             = (float*)pf;
    float* g             = (float*)pg;
    __nv_bfloat16* xb    = (__nv_bfloat16*)pxb;
    __nv_bfloat16* Whb   = (__nv_bfloat16*)pwh;
    __nv_bfloat16* hvb   = (__nv_bfloat16*)ph;
    float* logits        = (float*)pl;
    __nv_bfloat16* attnb = (__nv_bfloat16*)pab;

    const long sx  = (long)NC  * NTOK;
    const long sfg = (long)NC8 * NTOK;
    const long sat = (long)NTOK * NTOK;

    // 0) bf16 conversions
    {
        long n4 = (long)BATCH * NC * NTOK / 4;
        f32_to_bf16<<<(unsigned)((n4 + 255) / 256), 256>>>(x, xb, n4);
        long w4 = (long)NC * NC / 4;
        f32_to_bf16<<<(unsigned)((w4 + 255) / 256), 256>>>(Wh, Whb, w4);
    }

    // 1) f/g projections (fp32 SIMT)
    gemm128<false, 0><<<dim3(NTOK / BN, 1, BATCH), 256>>>(
        Wf, 0, NC, x, sx, NTOK, f, sfg, NTOK, bf, NC8, NC);
    gemm128<false, 0><<<dim3(NTOK / BN, 1, BATCH), 256>>>(
        Wg, 0, NC, x, sx, NTOK, g, sfg, NTOK, bg, NC8, NC);

    // 1b) hv = Whb @ xb + bh  (HMMA, bf16 out)
    gemm_mma<0><<<dim3(NTOK / 128, NC / 128, BATCH), 256>>>(
        Whb, 0, NC, xb, sx, NTOK, hvb, sx, NTOK, bh, nullptr, 0, nullptr, NC);

    // 2) logits = f^T g (fp32 SIMT)
    gemm128<true, 1><<<dim3(NTOK / BN, NTOK / BM, BATCH), 256>>>(
        f, sfg, NTOK, g, sfg, NTOK, logits, sat, NTOK, nullptr, NTOK, NC8);

    // 3) softmax (fp32 -> bf16)
    softmax_rows<<<dim3(NTOK, BATCH), 256>>>(logits, attnb);

    // 4) out = gamma * (hvb @ attn) + x  (HMMA, fused epilogue)
    gemm_mma<2><<<dim3(NTOK / 128, NC / 128, BATCH), 256>>>(
        hvb, sx, NTOK, attnb, sat, NTOK, out, sx, NTOK,
        nullptr, x, sx, gamma, NTOK);
}

// round 6
// speedup vs baseline: 1.6075x; 1.6019x over previous
#include <cuda_runtime.h>
#include <cuda_bf16.h>
#include <cstdint>

// ---------------------------------------------------------------------------
// B=4, C=512, C8=64, N=4096 — all GEMMs on HMMA (mma.sync bf16, fp32 accum)
// 0) convert: xb=bf16(x), Wfgb=bf16([Wf;Wg]) (128x512), Whb=bf16(Wh), bfg pack
// 1) fg = Wfgb@xb + bfg  (HMMA, bf16 out: rows 0-63 = f, 64-127 = g)
//    hv = Whb @xb + bh   (HMMA, bf16 out)
// 2) fT = transpose(f)   (4096x64 bf16)
// 3) logits = fT @ g     (HMMA, fp32 out)
// 4) softmax rows (fp32 in, bf16 out)
// 5) out = gamma * (hv @ attn) + x   (HMMA, fused epilogue)
// NOTE: tcgen05 unavailable (toolchain targets compute_103 w/o 'a' features).
// ---------------------------------------------------------------------------

#define BATCH 4
#define NC    512
#define NC8   64
#define NTOK  4096

__device__ __nv_bfloat16  d_xb    [(long)BATCH * NC  * NTOK];   //  16 MB
__device__ __nv_bfloat16  d_Wfgb  [(long)2 * NC8 * NC];         // 128 KB
__device__ __nv_bfloat16  d_Whb   [(long)NC * NC];              // 512 KB
__device__ float          d_bfg   [2 * NC8];
__device__ __nv_bfloat16  d_fgb   [(long)BATCH * 2 * NC8 * NTOK]; // 8 MB
__device__ __nv_bfloat16  d_fTb   [(long)BATCH * NTOK * NC8];   //   4 MB
__device__ __nv_bfloat16  d_hvb   [(long)BATCH * NC  * NTOK];   //  16 MB
__device__ float          d_logits[(long)BATCH * NTOK * NTOK];  // 256 MB
__device__ __nv_bfloat16  d_attnb [(long)BATCH * NTOK * NTOK];  // 128 MB

// ===========================================================================
// fp32 -> bf16 convert (vectorized)
// ===========================================================================
__global__ __launch_bounds__(256) void f32_to_bf16(
    const float* __restrict__ in, __nv_bfloat16* __restrict__ out, long n4)
{
    long i = (long)blockIdx.x * 256 + threadIdx.x;
    if (i >= n4) return;
    float4 v = ((const float4*)in)[i];
    __nv_bfloat162 p[2];
    p[0] = __floats2bfloat162_rn(v.x, v.y);
    p[1] = __floats2bfloat162_rn(v.z, v.w);
    ((uint2*)out)[i] = *(uint2*)p;
}

__global__ __launch_bounds__(128) void pack_bias(
    const float* __restrict__ bf, const float* __restrict__ bg,
    float* __restrict__ bfg)
{
    int t = threadIdx.x;
    bfg[t] = (t < NC8) ? bf[t] : bg[t - NC8];
}

// ===========================================================================
// bf16 64x64-tile transpose: fT[n, o] = f[o, n]   (f: 64 x 4096 per batch)
// ===========================================================================
__global__ __launch_bounds__(256) void transpose_f(
    const __nv_bfloat16* __restrict__ in, long sIn,
    __nv_bfloat16* __restrict__ outp)
{
    __shared__ __nv_bfloat16 t[64][72];
    const __nv_bfloat16* ip = in + (long)blockIdx.z * sIn;
    __nv_bfloat16* op = outp + (long)blockIdx.z * NTOK * NC8;
    const int j0 = blockIdx.x * 64;
    const int tid = threadIdx.x;

    #pragma unroll
    for (int pass = 0; pass < 4; pass++) {
        int v = tid + pass * 256;
        int r = v >> 4, c4 = v & 15;
        uint2 d = *(const uint2*)(ip + (long)r * NTOK + j0 + c4 * 4);
        *(uint2*)&t[r][c4 * 4] = d;
    }
    __syncthreads();
    #pragma unroll
    for (int pass = 0; pass < 4; pass++) {
        int v = tid + pass * 256;
        int r = v >> 4, c4 = v & 15;   // r = token within block, c4*4 = o
        __nv_bfloat16 tmp[4];
        tmp[0] = t[c4 * 4 + 0][r];
        tmp[1] = t[c4 * 4 + 1][r];
        tmp[2] = t[c4 * 4 + 2][r];
        tmp[3] = t[c4 * 4 + 3][r];
        *(uint2*)(op + (long)(j0 + r) * NC8 + c4 * 4) = *(uint2*)tmp;
    }
}

// ===========================================================================
// Row softmax: fp32 logits in, bf16 attn out.
// ===========================================================================
__global__ __launch_bounds__(256) void softmax_rows(
    const float* __restrict__ logits, __nv_bfloat16* __restrict__ attnb)
{
    const long row = (long)blockIdx.y * NTOK + blockIdx.x;
    const float* p = logits + row * NTOK;
    __nv_bfloat16* q = attnb + row * NTOK;
    const int tid = threadIdx.x;

    float v[16];
    float mx = -3.4e38f;
    #pragma unroll
    for (int t = 0; t < 16; t++) {
        v[t] = p[t * 256 + tid];
        mx = fmaxf(mx, v[t]);
    }

    __shared__ float sred[8];
    #pragma unroll
    for (int o = 16; o > 0; o >>= 1)
        mx = fmaxf(mx, __shfl_xor_sync(0xffffffffu, mx, o));
    if ((tid & 31) == 0) sred[tid >> 5] = mx;
    __syncthreads();
    if (tid == 0) {
        float m2 = sred[0];
        #pragma unroll
        for (int i = 1; i < 8; i++) m2 = fmaxf(m2, sred[i]);
        sred[0] = m2;
    }
    __syncthreads();
    const float rmax = sred[0];
    __syncthreads();

    float s = 0.f;
    #pragma unroll
    for (int t = 0; t < 16; t++) {
        v[t] = __expf(v[t] - rmax);
        s += v[t];
    }
    #pragma unroll
    for (int o = 16; o > 0; o >>= 1)
        s += __shfl_xor_sync(0xffffffffu, s, o);
    if ((tid & 31) == 0) sred[tid >> 5] = s;
    __syncthreads();
    if (tid == 0) {
        float s2 = 0.f;
        #pragma unroll
        for (int i = 0; i < 8; i++) s2 += sred[i];
        sred[0] = s2;
    }
    __syncthreads();
    const float inv = 1.0f / sred[0];

    #pragma unroll
    for (int t = 0; t < 16; t++)
        q[t * 256 + tid] = __float2bfloat16(v[t] * inv);
}

// ===========================================================================
// bf16 HMMA GEMM (mma.sync.m16n8k16), 128x128x32 tiles, 256 threads.
//   C[m,n] = sum_k A[m,k] * B[k,n]
//   A row-major (M x K), B row-major (K x N). ldmatrix.trans handles B.
// EPI=0: C(bf16) = acc + bias[m]
// EPI=1: C(f32)  = acc
// EPI=2: C(f32)  = gamma[0]*acc + resid[m,n]
// Requires M%128==0, N%128==0, K%32==0.
// ===========================================================================

__device__ __forceinline__ uint32_t smem_u32(const void* p) {
    uint32_t a;
    asm("{ .reg .u64 t; cvta.to.shared.u64 t, %1; cvt.u32.u64 %0, t; }"
        : "=r"(a) : "l"(p));
    return a;
}
__device__ __forceinline__ void cp16(uint32_t s, const void* g) {
    asm volatile("cp.async.cg.shared.global [%0], [%1], 16;" :: "r"(s), "l"(g));
}
__device__ __forceinline__ void ldsm_x4(uint32_t* r, uint32_t a) {
    asm volatile("ldmatrix.sync.aligned.m8n8.x4.shared.b16 {%0,%1,%2,%3}, [%4];"
                 : "=r"(r[0]), "=r"(r[1]), "=r"(r[2]), "=r"(r[3]) : "r"(a));
}
__device__ __forceinline__ void ldsm_x2_t(uint32_t* r, uint32_t a) {
    asm volatile("ldmatrix.sync.aligned.m8n8.x2.trans.shared.b16 {%0,%1}, [%2];"
                 : "=r"(r[0]), "=r"(r[1]) : "r"(a));
}
__device__ __forceinline__ void mma_bf16(float* d, const uint32_t* a, const uint32_t* b) {
    asm volatile(
        "mma.sync.aligned.m16n8k16.row.col.f32.bf16.bf16.f32 "
        "{%0,%1,%2,%3}, {%4,%5,%6,%7}, {%8,%9}, {%0,%1,%2,%3};"
        : "+f"(d[0]), "+f"(d[1]), "+f"(d[2]), "+f"(d[3])
        : "r"(a[0]), "r"(a[1]), "r"(a[2]), "r"(a[3]), "r"(b[0]), "r"(b[1]));
}

#define APAD 8
#define BPAD 8
#define ALD  (32 + APAD)    // bf16 elems per A smem row (80 B, 16B-aligned)
#define BLD  (128 + BPAD)   // bf16 elems per B smem row (272 B, 16B-aligned)

template<int EPI>
__global__ __launch_bounds__(256) void gemm_mma(
    const __nv_bfloat16* __restrict__ A, long sA, int ldA,
    const __nv_bfloat16* __restrict__ B, long sB, int ldB,
    void*                __restrict__ Cv, long sC, int ldC,
    const float* __restrict__ bias,
    const float* __restrict__ resid, long sR,
    const float* __restrict__ gamma,
    int K)
{
    __shared__ __nv_bfloat16 As[2][128][ALD];
    __shared__ __nv_bfloat16 Bs[2][32][BLD];

    const int b  = blockIdx.z;
    const int m0 = blockIdx.y * 128;
    const int n0 = blockIdx.x * 128;

    A += (long)b * sA;
    B += (long)b * sB;

    const int tid  = threadIdx.x;
    const int wid  = tid >> 5;
    const int lane = tid & 31;
    const int wm   = (wid >> 2) * 64;   // warp M offset (0/64)
    const int wn   = (wid & 3) * 32;    // warp N offset (0/32/64/96)

    float acc[4][4][4];
    #pragma unroll
    for (int i = 0; i < 4; i++)
        #pragma unroll
        for (int j = 0; j < 4; j++)
            #pragma unroll
            for (int r = 0; r < 4; r++) acc[i][j][r] = 0.f;

    const int aseg0 = tid * 2;
    const int bseg0 = tid * 2;

    auto load_stage = [&](int st, int k0) {
        #pragma unroll
        for (int p = 0; p < 2; p++) {
            int seg = aseg0 + p;
            int r = seg >> 2, sc = seg & 3;
            cp16(smem_u32(&As[st][r][sc * 8]),
                 A + (long)(m0 + r) * ldA + k0 + sc * 8);
        }
        #pragma unroll
        for (int p = 0; p < 2; p++) {
            int seg = bseg0 + p;
            int r = seg >> 4, sc = seg & 15;
            cp16(smem_u32(&Bs[st][r][sc * 8]),
                 B + (long)(k0 + r) * ldB + n0 + sc * 8);
        }
        asm volatile("cp.async.commit_group;");
    };

    const int KT = K >> 5;   // K / 32
    load_stage(0, 0);

    for (int kt = 0; kt < KT; kt++) {
        const int st = kt & 1;
        if (kt + 1 < KT) {
            load_stage(st ^ 1, (kt + 1) * 32);
            asm volatile("cp.async.wait_group 1;");
        } else {
            asm volatile("cp.async.wait_group 0;");
        }
        __syncthreads();

        #pragma unroll
        for (int kk = 0; kk < 2; kk++) {
            uint32_t af[4][4];
            #pragma unroll
            for (int mi = 0; mi < 4; mi++)
                ldsm_x4(af[mi], smem_u32(
                    &As[st][wm + mi * 16 + (lane & 15)][kk * 16 + ((lane >> 4) & 1) * 8]));
            uint32_t bf[4][2];
            #pragma unroll
            for (int ni = 0; ni < 4; ni++)
                ldsm_x2_t(bf[ni], smem_u32(
                    &Bs[st][kk * 16 + (lane & 15)][wn + ni * 8]));
            #pragma unroll
            for (int mi = 0; mi < 4; mi++)
                #pragma unroll
                for (int ni = 0; ni < 4; ni++)
                    mma_bf16(acc[mi][ni], af[mi], bf[ni]);
        }
        __syncthreads();
    }

    // ---- epilogue ----
    const int rbase = lane >> 2;        // 0..7
    const int cbase = (lane & 3) * 2;   // 0,2,4,6
    if (EPI == 0) {
        __nv_bfloat16* Cb = (__nv_bfloat16*)Cv + (long)b * sC;
        #pragma unroll
        for (int mi = 0; mi < 4; mi++) {
            #pragma unroll
            for (int ni = 0; ni < 4; ni++) {
                int row = m0 + wm + mi * 16 + rbase;
                int col = n0 + wn + ni * 8 + cbase;
                float bv0 = bias[row], bv1 = bias[row + 8];
                *(__nv_bfloat162*)&Cb[(long)row * ldC + col] =
                    __floats2bfloat162_rn(acc[mi][ni][0] + bv0, acc[mi][ni][1] + bv0);
                *(__nv_bfloat162*)&Cb[(long)(row + 8) * ldC + col] =
                    __floats2bfloat162_rn(acc[mi][ni][2] + bv1, acc[mi][ni][3] + bv1);
            }
        }
    } else if (EPI == 1) {
        float* Cf = (float*)Cv + (long)b * sC;
        #pragma unroll
        for (int mi = 0; mi < 4; mi++) {
            #pragma unroll
            for (int ni = 0; ni < 4; ni++) {
                int row = m0 + wm + mi * 16 + rbase;
                int col = n0 + wn + ni * 8 + cbase;
                float2 o0 = make_float2(acc[mi][ni][0], acc[mi][ni][1]);
                float2 o1 = make_float2(acc[mi][ni][2], acc[mi][ni][3]);
                *(float2*)&Cf[(long)row * ldC + col] = o0;
                *(float2*)&Cf[(long)(row + 8) * ldC + col] = o1;
            }
        }
    } else {
        float* Cf = (float*)Cv + (long)b * sC;
        const float* R = resid + (long)b * sR;
        const float gm = gamma[0];
        #pragma unroll
        for (int mi = 0; mi < 4; mi++) {
            #pragma unroll
            for (int ni = 0; ni < 4; ni++) {
                int row = m0 + wm + mi * 16 + rbase;
                int col = n0 + wn + ni * 8 + cbase;
                float2 r0 = *(const float2*)&R[(long)row * ldC + col];
                float2 r1 = *(const float2*)&R[(long)(row + 8) * ldC + col];
                float2 o0, o1;
                o0.x = gm * acc[mi][ni][0] + r0.x;
                o0.y = gm * acc[mi][ni][1] + r0.y;
                o1.x = gm * acc[mi][ni][2] + r1.x;
                o1.y = gm * acc[mi][ni][3] + r1.y;
                *(float2*)&Cf[(long)row * ldC + col] = o0;
                *(float2*)&Cf[(long)(row + 8) * ldC + col] = o1;
            }
        }
    }
}

// ===========================================================================
// kernel_launch  — inputs: x, Wf, bf, Wg, bg, Wh, bh, gamma
// ===========================================================================
extern "C" void kernel_launch(void* const* d_in, const int* in_sizes, int n_in,
                              void* d_out, int out_size)
{
    const float* x     = (const float*)d_in[0];
    const float* Wf    = (const float*)d_in[1];
    const float* bfp   = (const float*)d_in[2];
    const float* Wg    = (const float*)d_in[3];
    const float* bgp   = (const float*)d_in[4];
    const float* Wh    = (const float*)d_in[5];
    const float* bh    = (const float*)d_in[6];
    const float* gamma = (const float*)d_in[7];
    float* out = (float*)d_out;

    void *pxb, *pwfg, *pwh, *pbfg, *pfg, *pft, *ph, *pl, *pab;
    cudaGetSymbolAddress(&pxb,  d_xb);
    cudaGetSymbolAddress(&pwfg, d_Wfgb);
    cudaGetSymbolAddress(&pwh,  d_Whb);
    cudaGetSymbolAddress(&pbfg, d_bfg);
    cudaGetSymbolAddress(&pfg,  d_fgb);
    cudaGetSymbolAddress(&pft,  d_fTb);
    cudaGetSymbolAddress(&ph,   d_hvb);
    cudaGetSymbolAddress(&pl,   d_logits);
    cudaGetSymbolAddress(&pab,  d_attnb);
    __nv_bfloat16* xb    = (__nv_bfloat16*)pxb;
    __nv_bfloat16* Wfgb  = (__nv_bfloat16*)pwfg;
    __nv_bfloat16* Whb   = (__nv_bfloat16*)pwh;
    float*         bfg   = (float*)pbfg;
    __nv_bfloat16* fgb   = (__nv_bfloat16*)pfg;
    __nv_bfloat16* fTb   = (__nv_bfloat16*)pft;
    __nv_bfloat16* hvb   = (__nv_bfloat16*)ph;
    float*         logits = (float*)pl;
    __nv_bfloat16* attnb = (__nv_bfloat16*)pab;

    const long sx  = (long)NC * NTOK;         // x / hv / out batch stride
    const long sfg = (long)2 * NC8 * NTOK;    // fg batch stride
    const long sft = (long)NTOK * NC8;        // fT batch stride
    const long sat = (long)NTOK * NTOK;       // logits/attn batch stride

    // 0) conversions + bias pack
    {
        long n4 = (long)BATCH * NC * NTOK / 4;
        f32_to_bf16<<<(unsigned)((n4 + 255) / 256), 256>>>(x, xb, n4);
        long wfg4 = (long)NC8 * NC / 4;
        f32_to_bf16<<<(unsigned)((wfg4 + 255) / 256), 256>>>(Wf, Wfgb, wfg4);
        f32_to_bf16<<<(unsigned)((wfg4 + 255) / 256), 256>>>(Wg, Wfgb + (long)NC8 * NC, wfg4);
        long wh4 = (long)NC * NC / 4;
        f32_to_bf16<<<(unsigned)((wh4 + 255) / 256), 256>>>(Wh, Whb, wh4);
        pack_bias<<<1, 128>>>(bfp, bgp, bfg);
    }

    // 1) fg = Wfgb @ xb + bfg  (rows 0-63 = f, 64-127 = g)
    gemm_mma<0><<<dim3(NTOK / 128, 1, BATCH), 256>>>(
        Wfgb, 0, NC, xb, sx, NTOK, fgb, sfg, NTOK, bfg, nullptr, 0, nullptr, NC);

    // 1b) hv = Whb @ xb + bh
    gemm_mma<0><<<dim3(NTOK / 128, NC / 128, BATCH), 256>>>(
        Whb, 0, NC, xb, sx, NTOK, hvb, sx, NTOK, bh, nullptr, 0, nullptr, NC);

    // 2) fT = transpose(f)
    transpose_f<<<dim3(NTOK / 64, 1, BATCH), 256>>>(fgb, sfg, fTb);

    // 3) logits = fT @ g  (fp32 out)
    gemm_mma<1><<<dim3(NTOK / 128, NTOK / 128, BATCH), 256>>>(
        fTb, sft, NC8, fgb + (long)NC8 * NTOK, sfg, NTOK,
        logits, sat, NTOK, nullptr, nullptr, 0, nullptr, NC8);

    // 4) softmax (fp32 -> bf16)
    softmax_rows<<<dim3(NTOK, BATCH), 256>>>(logits, attnb);

    // 5) out = gamma * (hvb @ attn) + x
    gemm_mma<2><<<dim3(NTOK / 128, NC / 128, BATCH), 256>>>(
        hvb, sx, NTOK, attnb, sat, NTOK, out, sx, NTOK,
        nullptr, x, sx, gamma, NTOK);
}

// round 7
// speedup vs baseline: 1.6087x; 1.0008x over previous
#include <cuda_runtime.h>
#include <cuda_bf16.h>
#include <cstdint>

// ---------------------------------------------------------------------------
// B=4, C=512, C8=64, N=4096 — all GEMMs on HMMA (mma.sync bf16, fp32 accum)
// 0) convert: xb=bf16(x), Wfgb=bf16([Wf;Wg]) (128x512), Whb=bf16(Wh), bfg pack
// 1) fg = Wfgb@xb + bfg  (HMMA, bf16 out: rows 0-63 = f, 64-127 = g)
//    hv = Whb @xb + bh   (HMMA, bf16 out)
// 2) fT = transpose(f)   (4096x64 bf16)
// 3) logits = fT @ g     (HMMA, fp32 out)
// 4) softmax rows (fp32 in, bf16 out)
// 5) out = gamma * (hv @ attn) + x   (HMMA, fused epilogue)
// NOTE: tcgen05 unavailable (toolchain targets compute_103 w/o 'a' features).
// ---------------------------------------------------------------------------

#define BATCH 4
#define NC    512
#define NC8   64
#define NTOK  4096

__device__ __nv_bfloat16  d_xb    [(long)BATCH * NC  * NTOK];   //  16 MB
__device__ __nv_bfloat16  d_Wfgb  [(long)2 * NC8 * NC];         // 128 KB
__device__ __nv_bfloat16  d_Whb   [(long)NC * NC];              // 512 KB
__device__ float          d_bfg   [2 * NC8];
__device__ __nv_bfloat16  d_fgb   [(long)BATCH * 2 * NC8 * NTOK]; // 8 MB
__device__ __nv_bfloat16  d_fTb   [(long)BATCH * NTOK * NC8];   //   4 MB
__device__ __nv_bfloat16  d_hvb   [(long)BATCH * NC  * NTOK];   //  16 MB
__device__ float          d_logits[(long)BATCH * NTOK * NTOK];  // 256 MB
__device__ __nv_bfloat16  d_attnb [(long)BATCH * NTOK * NTOK];  // 128 MB

// ===========================================================================
// fp32 -> bf16 convert (vectorized)
// ===========================================================================
__global__ __launch_bounds__(256) void f32_to_bf16(
    const float* __restrict__ in, __nv_bfloat16* __restrict__ out, long n4)
{
    long i = (long)blockIdx.x * 256 + threadIdx.x;
    if (i >= n4) return;
    float4 v = ((const float4*)in)[i];
    __nv_bfloat162 p[2];
    p[0] = __floats2bfloat162_rn(v.x, v.y);
    p[1] = __floats2bfloat162_rn(v.z, v.w);
    ((uint2*)out)[i] = *(uint2*)p;
}

__global__ __launch_bounds__(128) void pack_bias(
    const float* __restrict__ bf, const float* __restrict__ bg,
    float* __restrict__ bfg)
{
    int t = threadIdx.x;
    bfg[t] = (t < NC8) ? bf[t] : bg[t - NC8];
}

// ===========================================================================
// bf16 64x64-tile transpose: fT[n, o] = f[o, n]   (f: 64 x 4096 per batch)
// ===========================================================================
__global__ __launch_bounds__(256) void transpose_f(
    const __nv_bfloat16* __restrict__ in, long sIn,
    __nv_bfloat16* __restrict__ outp)
{
    __shared__ __nv_bfloat16 t[64][72];
    const __nv_bfloat16* ip = in + (long)blockIdx.z * sIn;
    __nv_bfloat16* op = outp + (long)blockIdx.z * NTOK * NC8;
    const int j0 = blockIdx.x * 64;
    const int tid = threadIdx.x;

    #pragma unroll
    for (int pass = 0; pass < 4; pass++) {
        int v = tid + pass * 256;
        int r = v >> 4, c4 = v & 15;
        uint2 d = *(const uint2*)(ip + (long)r * NTOK + j0 + c4 * 4);
        *(uint2*)&t[r][c4 * 4] = d;
    }
    __syncthreads();
    #pragma unroll
    for (int pass = 0; pass < 4; pass++) {
        int v = tid + pass * 256;
        int r = v >> 4, c4 = v & 15;   // r = token within block, c4*4 = o
        __nv_bfloat16 tmp[4];
        tmp[0] = t[c4 * 4 + 0][r];
        tmp[1] = t[c4 * 4 + 1][r];
        tmp[2] = t[c4 * 4 + 2][r];
        tmp[3] = t[c4 * 4 + 3][r];
        *(uint2*)(op + (long)(j0 + r) * NC8 + c4 * 4) = *(uint2*)tmp;
    }
}

// ===========================================================================
// Row softmax: fp32 logits in, bf16 attn out.
// ===========================================================================
__global__ __launch_bounds__(256) void softmax_rows(
    const float* __restrict__ logits, __nv_bfloat16* __restrict__ attnb)
{
    const long row = (long)blockIdx.y * NTOK + blockIdx.x;
    const float* p = logits + row * NTOK;
    __nv_bfloat16* q = attnb + row * NTOK;
    const int tid = threadIdx.x;

    float v[16];
    float mx = -3.4e38f;
    #pragma unroll
    for (int t = 0; t < 16; t++) {
        v[t] = p[t * 256 + tid];
        mx = fmaxf(mx, v[t]);
    }

    __shared__ float sred[8];
    #pragma unroll
    for (int o = 16; o > 0; o >>= 1)
        mx = fmaxf(mx, __shfl_xor_sync(0xffffffffu, mx, o));
    if ((tid & 31) == 0) sred[tid >> 5] = mx;
    __syncthreads();
    if (tid == 0) {
        float m2 = sred[0];
        #pragma unroll
        for (int i = 1; i < 8; i++) m2 = fmaxf(m2, sred[i]);
        sred[0] = m2;
    }
    __syncthreads();
    const float rmax = sred[0];
    __syncthreads();

    float s = 0.f;
    #pragma unroll
    for (int t = 0; t < 16; t++) {
        v[t] = __expf(v[t] - rmax);
        s += v[t];
    }
    #pragma unroll
    for (int o = 16; o > 0; o >>= 1)
        s += __shfl_xor_sync(0xffffffffu, s, o);
    if ((tid & 31) == 0) sred[tid >> 5] = s;
    __syncthreads();
    if (tid == 0) {
        float s2 = 0.f;
        #pragma unroll
        for (int i = 0; i < 8; i++) s2 += sred[i];
        sred[0] = s2;
    }
    __syncthreads();
    const float inv = 1.0f / sred[0];

    #pragma unroll
    for (int t = 0; t < 16; t++)
        q[t * 256 + tid] = __float2bfloat16(v[t] * inv);
}

// ===========================================================================
// bf16 HMMA GEMM (mma.sync.m16n8k16), 128x128x32 tiles, 256 threads.
//   C[m,n] = sum_k A[m,k] * B[k,n]
//   A row-major (M x K), B row-major (K x N). ldmatrix.trans handles B.
// EPI=0: C(bf16) = acc + bias[m]
// EPI=1: C(f32)  = acc
// EPI=2: C(f32)  = gamma[0]*acc + resid[m,n]
// Requires M%128==0, N%128==0, K%32==0.
// ===========================================================================

__device__ __forceinline__ uint32_t smem_u32(const void* p) {
    uint32_t a;
    asm("{ .reg .u64 t; cvta.to.shared.u64 t, %1; cvt.u32.u64 %0, t; }"
        : "=r"(a) : "l"(p));
    return a;
}
__device__ __forceinline__ void cp16(uint32_t s, const void* g) {
    asm volatile("cp.async.cg.shared.global [%0], [%1], 16;" :: "r"(s), "l"(g));
}
__device__ __forceinline__ void ldsm_x4(uint32_t* r, uint32_t a) {
    asm volatile("ldmatrix.sync.aligned.m8n8.x4.shared.b16 {%0,%1,%2,%3}, [%4];"
                 : "=r"(r[0]), "=r"(r[1]), "=r"(r[2]), "=r"(r[3]) : "r"(a));
}
__device__ __forceinline__ void ldsm_x2_t(uint32_t* r, uint32_t a) {
    asm volatile("ldmatrix.sync.aligned.m8n8.x2.trans.shared.b16 {%0,%1}, [%2];"
                 : "=r"(r[0]), "=r"(r[1]) : "r"(a));
}
__device__ __forceinline__ void mma_bf16(float* d, const uint32_t* a, const uint32_t* b) {
    asm volatile(
        "mma.sync.aligned.m16n8k16.row.col.f32.bf16.bf16.f32 "
        "{%0,%1,%2,%3}, {%4,%5,%6,%7}, {%8,%9}, {%0,%1,%2,%3};"
        : "+f"(d[0]), "+f"(d[1]), "+f"(d[2]), "+f"(d[3])
        : "r"(a[0]), "r"(a[1]), "r"(a[2]), "r"(a[3]), "r"(b[0]), "r"(b[1]));
}

#define APAD 8
#define BPAD 8
#define ALD  (32 + APAD)    // bf16 elems per A smem row (80 B, 16B-aligned)
#define BLD  (128 + BPAD)   // bf16 elems per B smem row (272 B, 16B-aligned)

template<int EPI>
__global__ __launch_bounds__(256) void gemm_mma(
    const __nv_bfloat16* __restrict__ A, long sA, int ldA,
    const __nv_bfloat16* __restrict__ B, long sB, int ldB,
    void*                __restrict__ Cv, long sC, int ldC,
    const float* __restrict__ bias,
    const float* __restrict__ resid, long sR,
    const float* __restrict__ gamma,
    int K)
{
    __shared__ __nv_bfloat16 As[2][128][ALD];
    __shared__ __nv_bfloat16 Bs[2][32][BLD];

    const int b  = blockIdx.z;
    const int m0 = blockIdx.y * 128;
    const int n0 = blockIdx.x * 128;

    A += (long)b * sA;
    B += (long)b * sB;

    const int tid  = threadIdx.x;
    const int wid  = tid >> 5;
    const int lane = tid & 31;
    const int wm   = (wid >> 2) * 64;   // warp M offset (0/64)
    const int wn   = (wid & 3) * 32;    // warp N offset (0/32/64/96)

    float acc[4][4][4];
    #pragma unroll
    for (int i = 0; i < 4; i++)
        #pragma unroll
        for (int j = 0; j < 4; j++)
            #pragma unroll
            for (int r = 0; r < 4; r++) acc[i][j][r] = 0.f;

    const int aseg0 = tid * 2;
    const int bseg0 = tid * 2;

    auto load_stage = [&](int st, int k0) {
        #pragma unroll
        for (int p = 0; p < 2; p++) {
            int seg = aseg0 + p;
            int r = seg >> 2, sc = seg & 3;
            cp16(smem_u32(&As[st][r][sc * 8]),
                 A + (long)(m0 + r) * ldA + k0 + sc * 8);
        }
        #pragma unroll
        for (int p = 0; p < 2; p++) {
            int seg = bseg0 + p;
            int r = seg >> 4, sc = seg & 15;
            cp16(smem_u32(&Bs[st][r][sc * 8]),
                 B + (long)(k0 + r) * ldB + n0 + sc * 8);
        }
        asm volatile("cp.async.commit_group;");
    };

    const int KT = K >> 5;   // K / 32
    load_stage(0, 0);

    for (int kt = 0; kt < KT; kt++) {
        const int st = kt & 1;
        if (kt + 1 < KT) {
            load_stage(st ^ 1, (kt + 1) * 32);
            asm volatile("cp.async.wait_group 1;");
        } else {
            asm volatile("cp.async.wait_group 0;");
        }
        __syncthreads();

        #pragma unroll
        for (int kk = 0; kk < 2; kk++) {
            uint32_t af[4][4];
            #pragma unroll
            for (int mi = 0; mi < 4; mi++)
                ldsm_x4(af[mi], smem_u32(
                    &As[st][wm + mi * 16 + (lane & 15)][kk * 16 + ((lane >> 4) & 1) * 8]));
            uint32_t bf[4][2];
            #pragma unroll
            for (int ni = 0; ni < 4; ni++)
                ldsm_x2_t(bf[ni], smem_u32(
                    &Bs[st][kk * 16 + (lane & 15)][wn + ni * 8]));
            #pragma unroll
            for (int mi = 0; mi < 4; mi++)
                #pragma unroll
                for (int ni = 0; ni < 4; ni++)
                    mma_bf16(acc[mi][ni], af[mi], bf[ni]);
        }
        __syncthreads();
    }

    // ---- epilogue ----
    const int rbase = lane >> 2;        // 0..7
    const int cbase = (lane & 3) * 2;   // 0,2,4,6
    if (EPI == 0) {
        __nv_bfloat16* Cb = (__nv_bfloat16*)Cv + (long)b * sC;
        #pragma unroll
        for (int mi = 0; mi < 4; mi++) {
            #pragma unroll
            for (int ni = 0; ni < 4; ni++) {
                int row = m0 + wm + mi * 16 + rbase;
                int col = n0 + wn + ni * 8 + cbase;
                float bv0 = bias[row], bv1 = bias[row + 8];
                *(__nv_bfloat162*)&Cb[(long)row * ldC + col] =
                    __floats2bfloat162_rn(acc[mi][ni][0] + bv0, acc[mi][ni][1] + bv0);
                *(__nv_bfloat162*)&Cb[(long)(row + 8) * ldC + col] =
                    __floats2bfloat162_rn(acc[mi][ni][2] + bv1, acc[mi][ni][3] + bv1);
            }
        }
    } else if (EPI == 1) {
        float* Cf = (float*)Cv + (long)b * sC;
        #pragma unroll
        for (int mi = 0; mi < 4; mi++) {
            #pragma unroll
            for (int ni = 0; ni < 4; ni++) {
                int row = m0 + wm + mi * 16 + rbase;
                int col = n0 + wn + ni * 8 + cbase;
                float2 o0 = make_float2(acc[mi][ni][0], acc[mi][ni][1]);
                float2 o1 = make_float2(acc[mi][ni][2], acc[mi][ni][3]);
                *(float2*)&Cf[(long)row * ldC + col] = o0;
                *(float2*)&Cf[(long)(row + 8) * ldC + col] = o1;
            }
        }
    } else {
        float* Cf = (float*)Cv + (long)b * sC;
        const float* R = resid + (long)b * sR;
        const float gm = gamma[0];
        #pragma unroll
        for (int mi = 0; mi < 4; mi++) {
            #pragma unroll
            for (int ni = 0; ni < 4; ni++) {
                int row = m0 + wm + mi * 16 + rbase;
                int col = n0 + wn + ni * 8 + cbase;
                float2 r0 = *(const float2*)&R[(long)row * ldC + col];
                float2 r1 = *(const float2*)&R[(long)(row + 8) * ldC + col];
                float2 o0, o1;
                o0.x = gm * acc[mi][ni][0] + r0.x;
                o0.y = gm * acc[mi][ni][1] + r0.y;
                o1.x = gm * acc[mi][ni][2] + r1.x;
                o1.y = gm * acc[mi][ni][3] + r1.y;
                *(float2*)&Cf[(long)row * ldC + col] = o0;
                *(float2*)&Cf[(long)(row + 8) * ldC + col] = o1;
            }
        }
    }
}

// ===========================================================================
// kernel_launch  — inputs: x, Wf, bf, Wg, bg, Wh, bh, gamma
// ===========================================================================
extern "C" void kernel_launch(void* const* d_in, const int* in_sizes, int n_in,
                              void* d_out, int out_size)
{
    const float* x     = (const float*)d_in[0];
    const float* Wf    = (const float*)d_in[1];
    const float* bfp   = (const float*)d_in[2];
    const float* Wg    = (const float*)d_in[3];
    const float* bgp   = (const float*)d_in[4];
    const float* Wh    = (const float*)d_in[5];
    const float* bh    = (const float*)d_in[6];
    const float* gamma = (const float*)d_in[7];
    float* out = (float*)d_out;

    void *pxb, *pwfg, *pwh, *pbfg, *pfg, *pft, *ph, *pl, *pab;
    cudaGetSymbolAddress(&pxb,  d_xb);
    cudaGetSymbolAddress(&pwfg, d_Wfgb);
    cudaGetSymbolAddress(&pwh,  d_Whb);
    cudaGetSymbolAddress(&pbfg, d_bfg);
    cudaGetSymbolAddress(&pfg,  d_fgb);
    cudaGetSymbolAddress(&pft,  d_fTb);
    cudaGetSymbolAddress(&ph,   d_hvb);
    cudaGetSymbolAddress(&pl,   d_logits);
    cudaGetSymbolAddress(&pab,  d_attnb);
    __nv_bfloat16* xb    = (__nv_bfloat16*)pxb;
    __nv_bfloat16* Wfgb  = (__nv_bfloat16*)pwfg;
    __nv_bfloat16* Whb   = (__nv_bfloat16*)pwh;
    float*         bfg   = (float*)pbfg;
    __nv_bfloat16* fgb   = (__nv_bfloat16*)pfg;
    __nv_bfloat16* fTb   = (__nv_bfloat16*)pft;
    __nv_bfloat16* hvb   = (__nv_bfloat16*)ph;
    float*         logits = (float*)pl;
    __nv_bfloat16* attnb = (__nv_bfloat16*)pab;

    const long sx  = (long)NC * NTOK;         // x / hv / out batch stride
    const long sfg = (long)2 * NC8 * NTOK;    // fg batch stride
    const long sft = (long)NTOK * NC8;        // fT batch stride
    const long sat = (long)NTOK * NTOK;       // logits/attn batch stride

    // 0) conversions + bias pack
    {
        long n4 = (long)BATCH * NC * NTOK / 4;
        f32_to_bf16<<<(unsigned)((n4 + 255) / 256), 256>>>(x, xb, n4);
        long wfg4 = (long)NC8 * NC / 4;
        f32_to_bf16<<<(unsigned)((wfg4 + 255) / 256), 256>>>(Wf, Wfgb, wfg4);
        f32_to_bf16<<<(unsigned)((wfg4 + 255) / 256), 256>>>(Wg, Wfgb + (long)NC8 * NC, wfg4);
        long wh4 = (long)NC * NC / 4;
        f32_to_bf16<<<(unsigned)((wh4 + 255) / 256), 256>>>(Wh, Whb, wh4);
        pack_bias<<<1, 128>>>(bfp, bgp, bfg);
    }

    // 1) fg = Wfgb @ xb + bfg  (rows 0-63 = f, 64-127 = g)
    gemm_mma<0><<<dim3(NTOK / 128, 1, BATCH), 256>>>(
        Wfgb, 0, NC, xb, sx, NTOK, fgb, sfg, NTOK, bfg, nullptr, 0, nullptr, NC);

    // 1b) hv = Whb @ xb + bh
    gemm_mma<0><<<dim3(NTOK / 128, NC / 128, BATCH), 256>>>(
        Whb, 0, NC, xb, sx, NTOK, hvb, sx, NTOK, bh, nullptr, 0, nullptr, NC);

    // 2) fT = transpose(f)
    transpose_f<<<dim3(NTOK / 64, 1, BATCH), 256>>>(fgb, sfg, fTb);

    // 3) logits = fT @ g  (fp32 out)
    gemm_mma<1><<<dim3(NTOK / 128, NTOK / 128, BATCH), 256>>>(
        fTb, sft, NC8, fgb + (long)NC8 * NTOK, sfg, NTOK,
        logits, sat, NTOK, nullptr, nullptr, 0, nullptr, NC8);

    // 4) softmax (fp32 -> bf16)
    softmax_rows<<<dim3(NTOK, BATCH), 256>>>(logits, attnb);

    // 5) out = gamma * (hvb @ attn) + x
    gemm_mma<2><<<dim3(NTOK / 128, NC / 128, BATCH), 256>>>(
        hvb, sx, NTOK, attnb, sat, NTOK, out, sx, NTOK,
        nullptr, x, sx, gamma, NTOK);
}